// round 8
// baseline (speedup 1.0000x reference)
#include <cuda_runtime.h>

#define NPTS 4096
#define TPB 256
#define ITILES 8             // 8 i-tiles x 512 i each (2 queries/thread)
#define JCHUNKS 74           // 8*74 = 592 blocks = exactly one wave @ 4 CTAs/SM (148 SMs)
#define CHUNK 56             // 74*56 = 4144 >= 4096, padded, branch-free
#define NBLOCKS (ITILES * JCHUNKS)
#define FING 128             // finalize: 128 blocks x 32 i's (lane = i) = 4096

typedef unsigned long long u64;

__device__ float4 g_pden[JCHUNKS * NPTS];
__device__ float4 g_pnum[JCHUNKS * NPTS];
__device__ unsigned g_ctr  = 0;
__device__ unsigned g_done = 0;

__device__ __forceinline__ float ex2f(float x) {
    float y;
    asm("ex2.approx.ftz.f32 %0, %1;" : "=f"(y) : "f"(x));
    return y;
}
__device__ __forceinline__ u64 pack2(float lo, float hi) {
    u64 r; asm("mov.b64 %0, {%1, %2};" : "=l"(r) : "f"(lo), "f"(hi)); return r;
}
__device__ __forceinline__ void unpack2(u64 v, float& lo, float& hi) {
    asm("mov.b64 {%0, %1}, %2;" : "=f"(lo), "=f"(hi) : "l"(v));
}
__device__ __forceinline__ u64 fma2(u64 a, u64 b, u64 c) {
    u64 d; asm("fma.rn.f32x2 %0, %1, %2, %3;" : "=l"(d) : "l"(a), "l"(b), "l"(c)); return d;
}
__device__ __forceinline__ u64 add2(u64 a, u64 b) {
    u64 d; asm("add.rn.f32x2 %0, %1, %2;" : "=l"(d) : "l"(a), "l"(b)); return d;
}
// fixed fma order so hot loop, prep and finalize produce identical bits
__device__ __forceinline__ float dotw(float4 r, const float* __restrict__ W, int c) {
    float d = r.x * __ldg(W + c*4 + 0);
    d = fmaf(r.y, __ldg(W + c*4 + 1), d);
    d = fmaf(r.z, __ldg(W + c*4 + 2), d);
    d = fmaf(r.w, __ldg(W + c*4 + 3), d);
    return d;
}

// k'_{j,i,c} = 2^{a_j*(2 b_i) - a_j^2}; the per-i factor 2^{-b_i^2} cancels in the ratio.
// s = sqrt(0.5*log2 e)/h. Channel values for queries A,B are packed as f32x2 pairs.
__global__ void __launch_bounds__(TPB, 4) fused_kernel(
    const float* __restrict__ x,   // [4096,4]
    const float* __restrict__ tx,  // [4096,4]
    const float* __restrict__ Y,   // [4096,3]
    const float* __restrict__ W,   // [3,4]
    const float* __restrict__ h,   // [1]
    float* __restrict__ out)       // [4096,3]
{
    // per-j 80B: {(a0,a0),(a1,a1)} {(a2,a2),(nq0,nq0)} {(nq1,nq1),(nq2,nq2)}
    //            {(y0,y0),(y1,y1)} {(y2,y2), --}     (nq = -a^2, pre-negated)
    __shared__ ulonglong2 sV[CHUNK * 5];

    const int tid = threadIdx.x, bx = blockIdx.x, by = blockIdx.y;
    const float s  = sqrtf(0.5f * 1.44269504088896340736f) / __ldg(h);
    const float s2 = s + s;

    // ---- prep this block's j-chunk (one row per thread, tid < CHUNK) ----
    if (tid < CHUNK) {
        int j = by * CHUNK + tid;
        float a0, a1, a2, q0, q1, q2, y0, y1, y2;
        if (j < NPTS) {
            float4 xt = __ldg(reinterpret_cast<const float4*>(tx) + j);
            a0 = dotw(xt, W, 0) * s; a1 = dotw(xt, W, 1) * s; a2 = dotw(xt, W, 2) * s;
            q0 = -(a0*a0); q1 = -(a1*a1); q2 = -(a2*a2);
            y0 = __ldg(Y+3*j); y1 = __ldg(Y+3*j+1); y2 = __ldg(Y+3*j+2);
        } else {
            a0 = a1 = a2 = 0.f; q0 = q1 = q2 = -3e38f;  // ex2 -> 0, no contribution
            y0 = y1 = y2 = 0.f;
        }
        sV[tid*5+0] = make_ulonglong2(pack2(a0,a0), pack2(a1,a1));
        sV[tid*5+1] = make_ulonglong2(pack2(a2,a2), pack2(q0,q0));
        sV[tid*5+2] = make_ulonglong2(pack2(q1,q1), pack2(q2,q2));
        sV[tid*5+3] = make_ulonglong2(pack2(y0,y0), pack2(y1,y1));
        sV[tid*5+4] = make_ulonglong2(pack2(y2,y2), 0ull);
    }

    // ---- two query points per thread; t-pairs packed (A,B) per channel ----
    const int iA = bx * (2*TPB) + tid;
    const int iB = iA + TPB;
    float4 xqA = __ldg(reinterpret_cast<const float4*>(x) + iA);
    float4 xqB = __ldg(reinterpret_cast<const float4*>(x) + iB);
    const u64 tp0 = pack2(dotw(xqA,W,0)*s2, dotw(xqB,W,0)*s2);
    const u64 tp1 = pack2(dotw(xqA,W,1)*s2, dotw(xqB,W,1)*s2);
    const u64 tp2 = pack2(dotw(xqA,W,2)*s2, dotw(xqB,W,2)*s2);
    __syncthreads();

    // ---- hot loop: 6 EX2 per j, packed args + packed accumulation ----
    u64 d0 = 0, d1 = 0, d2 = 0, n0 = 0, n1 = 0, n2 = 0;  // (0.f,0.f) pairs
#pragma unroll 4
    for (int t = 0; t < CHUNK; ++t) {
        ulonglong2 u0 = sV[t*5+0], u1 = sV[t*5+1], u2 = sV[t*5+2], u3 = sV[t*5+3];
        u64 yp2 = sV[t*5+4].x;
        u64 g0 = fma2(u0.x, tp0, u1.y);   // (a0,a0)*(tA0,tB0)+(nq0,nq0)
        u64 g1 = fma2(u0.y, tp1, u2.x);
        u64 g2 = fma2(u1.x, tp2, u2.y);
        float ga, gb;
        unpack2(g0, ga, gb); u64 e0 = pack2(ex2f(ga), ex2f(gb));
        unpack2(g1, ga, gb); u64 e1 = pack2(ex2f(ga), ex2f(gb));
        unpack2(g2, ga, gb); u64 e2 = pack2(ex2f(ga), ex2f(gb));
        d0 = add2(d0, e0); n0 = fma2(e0, u3.x, n0);
        d1 = add2(d1, e1); n1 = fma2(e1, u3.y, n1);
        d2 = add2(d2, e2); n2 = fma2(e2, yp2, n2);
    }

    // ---- store partials (unpack A/B halves) ----
    {
        float dA0,dB0,dA1,dB1,dA2,dB2, nA0,nB0,nA1,nB1,nA2,nB2;
        unpack2(d0,dA0,dB0); unpack2(d1,dA1,dB1); unpack2(d2,dA2,dB2);
        unpack2(n0,nA0,nB0); unpack2(n1,nA1,nB1); unpack2(n2,nA2,nB2);
        g_pden[by*NPTS + iA] = make_float4(dA0,dA1,dA2,0.f);
        g_pnum[by*NPTS + iA] = make_float4(nA0,nA1,nA2,0.f);
        g_pden[by*NPTS + iB] = make_float4(dB0,dB1,dB2,0.f);
        g_pnum[by*NPTS + iB] = make_float4(nB0,nB1,nB2,0.f);
    }

    // ---- publish + device-wide ticket barrier (grid = exactly one wave) ----
    __threadfence();
    __syncthreads();
    if (tid == 0) {
        atomicAdd(&g_ctr, 1u);
        while (*((volatile unsigned*)&g_ctr) < NBLOCKS) __nanosleep(32);
    }
    __syncthreads();
    __threadfence();  // acquire

    // ---- finalize: first FING blocks, warp0 only, lane = i (coalesced reads) ----
    const int flat = by * ITILES + bx;
    if (flat < FING && tid < 32) {
        const int i = flat * 32 + tid;
        float D0=0.f,D1=0.f,D2=0.f, N0=0.f,N1=0.f,N2=0.f;
#pragma unroll 2
        for (int z = 0; z < JCHUNKS; ++z) {
            float4 pd = g_pden[z*NPTS + i];
            float4 pn = g_pnum[z*NPTS + i];
            D0 += pd.x; D1 += pd.y; D2 += pd.z;
            N0 += pn.x; N1 += pn.y; N2 += pn.z;
        }
        // self-pair (leave-one-out): bit-identical recompute
        float4 xt = __ldg(reinterpret_cast<const float4*>(tx) + i);
        float4 xq = __ldg(reinterpret_cast<const float4*>(x) + i);
        float a0 = dotw(xt,W,0)*s,  a1 = dotw(xt,W,1)*s,  a2 = dotw(xt,W,2)*s;
        float t0 = dotw(xq,W,0)*s2, t1 = dotw(xq,W,1)*s2, t2 = dotw(xq,W,2)*s2;
        float k0 = ex2f(fmaf(a0, t0, -(a0*a0)));
        float k1 = ex2f(fmaf(a1, t1, -(a1*a1)));
        float k2 = ex2f(fmaf(a2, t2, -(a2*a2)));
        float y0 = __ldg(Y+3*i), y1 = __ldg(Y+3*i+1), y2 = __ldg(Y+3*i+2);
        out[3*i+0] = (N0 - k0*y0) / (D0 - k0);
        out[3*i+1] = (N1 - k1*y1) / (D1 - k1);
        out[3*i+2] = (N2 - k2*y2) / (D2 - k2);
    }

    // ---- last block resets counters -> stateless across graph replays ----
    __syncthreads();
    if (tid == 0) {
        unsigned v = atomicAdd(&g_done, 1u);
        if (v == NBLOCKS - 1) { g_ctr = 0; g_done = 0; __threadfence(); }
    }
}

extern "C" void kernel_launch(void* const* d_in, const int* in_sizes, int n_in,
                              void* d_out, int out_size) {
    const float* x  = (const float*)d_in[0];
    const float* tx = (const float*)d_in[1];
    const float* Y  = (const float*)d_in[2];
    const float* W  = (const float*)d_in[3];
    const float* h  = (const float*)d_in[4];
    float* out = (float*)d_out;

    fused_kernel<<<dim3(ITILES, JCHUNKS), TPB>>>(x, tx, Y, W, h, out);
}